// round 2
// baseline (speedup 1.0000x reference)
#include <cuda_runtime.h>
#include <cuda_bf16.h>

#define BATCH 256

// ---------------- scratch (static device globals: allocation-free) ----------
__device__ float d_conv1[BATCH * 8  * 32 * 32];
__device__ float d_pool1[BATCH * 8  * 16 * 16];
__device__ float d_conv2[BATCH * 16 * 16 * 16];
__device__ float d_pool2[BATCH * 16 * 8  * 8];
__device__ float d_conv3[BATCH * 32 * 8  * 8];
__device__ float d_pool3[BATCH * 32 * 4  * 4];
// combined weights: [n_otile][F][7 slots][8 ch], slot0 = base_w, slots1..6 = spline_w*scaler
__device__ float d_sw1[1 * 27  * 7 * 8];
__device__ float d_sw2[2 * 72  * 7 * 8];
__device__ float d_sw3[4 * 144 * 7 * 8];
__device__ float d_wt [512 * 100];   // transposed lin_w: [k][o]

// ---------------- weight prep --------------------------------------------
__global__ void prep_sw_kernel(const float* __restrict__ base_w,
                               const float* __restrict__ spline_w,
                               const float* __restrict__ scaler,
                               float* __restrict__ sw, int O, int F) {
    int idx = blockIdx.x * blockDim.x + threadIdx.x;
    int total = O * F * 7;
    if (idx >= total) return;
    int slot = idx % 7;
    int f    = (idx / 7) % F;
    int o    = idx / (7 * F);
    float v;
    if (slot == 0) v = base_w[o * F + f];
    else           v = spline_w[(o * F + f) * 6 + (slot - 1)] * scaler[o * F + f];
    int tile = o >> 3, j = o & 7;
    sw[((tile * F + f) * 7 + slot) * 8 + j] = v;
}

__global__ void prep_wt_kernel(const float* __restrict__ w, float* __restrict__ wt) {
    int idx = blockIdx.x * blockDim.x + threadIdx.x;   // 100*512
    if (idx >= 100 * 512) return;
    int o = idx / 512, k = idx % 512;
    wt[k * 100 + o] = w[idx];
}

// ---------------- fused KAN 3x3 conv -------------------------------------
// One thread = one conv output position (pre-pool) x one tile of 8 output
// channels. Weight smem reads are warp-uniform (broadcast, conflict-free).
template<int C, int HW, int NTILE>
__global__ void __launch_bounds__(256)
conv_kan_kernel(const float* __restrict__ X,     // [B][C][HW][HW]
                const float* __restrict__ SW,    // [NTILE][F][7][8]
                float* __restrict__ Y) {         // [B][NTILE*8][HW][HW]
    constexpr int F = C * 9;
    constexpr int O = NTILE * 8;
    __shared__ float sw[F * 7 * 8];

    const float* gsw = SW + blockIdx.y * (F * 7 * 8);
    for (int i = threadIdx.x; i < F * 7 * 8 / 4; i += blockDim.x)
        reinterpret_cast<float4*>(sw)[i] = reinterpret_cast<const float4*>(gsw)[i];
    __syncthreads();

    int p = blockIdx.x * blockDim.x + threadIdx.x;
    if (p >= BATCH * HW * HW) return;
    int x = p % HW;
    int y = (p / HW) % HW;
    int b = p / (HW * HW);

    float acc[8];
#pragma unroll
    for (int j = 0; j < 8; j++) acc[j] = 0.f;

    const float* Xb = X + (long)b * C * HW * HW;
    for (int c = 0; c < C; c++) {
        const float* Xc = Xb + c * HW * HW;
#pragma unroll
        for (int ky = 0; ky < 3; ky++) {
            int yy = y + ky - 1;
            bool yok = (unsigned)yy < (unsigned)HW;
#pragma unroll
            for (int kx = 0; kx < 3; kx++) {
                int xx = x + kx - 1;
                float v = (yok && (unsigned)xx < (unsigned)HW) ? Xc[yy * HW + xx] : 0.f;

                // ---- slot values: silu + 6 cubic B-spline bases ----
                float sv[7];
                sv[0] = v * (1.f / (1.f + __expf(-v)));      // silu

                float t  = (v + 3.f) * 1.5f;                 // (x - grid0)/h
                bool valid = (t >= 0.f) && (t < 9.f);
                float fi = floorf(t);
                int   i0 = (int)fi;
                float u  = t - fi;
                float u2 = u * u, u3 = u2 * u;
                float q3 = u3 * (1.f / 6.f);                          // B_{i0}
                float q2 = ((3.f * u2 - 3.f * u3) + 3.f * u + 1.f) * (1.f / 6.f); // B_{i0-1}
                float q1 = (3.f * u3 - 6.f * u2 + 4.f) * (1.f / 6.f); // B_{i0-2}
                float iu = 1.f - u;
                float q0 = iu * iu * iu * (1.f / 6.f);                // B_{i0-3}
                if (!valid) { q0 = q1 = q2 = q3 = 0.f; i0 = -1000; }
#pragma unroll
                for (int m = 0; m < 6; m++) {
                    int d = i0 - m;
                    float r = (d == 0) ? q3 : (d == 1) ? q2 : (d == 2) ? q1
                            : (d == 3) ? q0 : 0.f;
                    sv[1 + m] = r;
                }

                // ---- accumulate 7 slots x 8 channels (broadcast LDS) ----
                const float* wp = sw + (c * 9 + ky * 3 + kx) * 56;
#pragma unroll
                for (int s = 0; s < 7; s++) {
                    float4 wa = *reinterpret_cast<const float4*>(wp + s * 8);
                    float4 wb = *reinterpret_cast<const float4*>(wp + s * 8 + 4);
                    float sval = sv[s];
                    acc[0] = fmaf(sval, wa.x, acc[0]);
                    acc[1] = fmaf(sval, wa.y, acc[1]);
                    acc[2] = fmaf(sval, wa.z, acc[2]);
                    acc[3] = fmaf(sval, wa.w, acc[3]);
                    acc[4] = fmaf(sval, wb.x, acc[4]);
                    acc[5] = fmaf(sval, wb.y, acc[5]);
                    acc[6] = fmaf(sval, wb.z, acc[6]);
                    acc[7] = fmaf(sval, wb.w, acc[7]);
                }
            }
        }
    }

    float* Yp = Y + (((long)b * O + blockIdx.y * 8) * HW + y) * HW + x;
#pragma unroll
    for (int j = 0; j < 8; j++) Yp[j * HW * HW] = acc[j];
}

// ---------------- 2x2 maxpool --------------------------------------------
__global__ void maxpool_kernel(const float* __restrict__ X, float* __restrict__ Y,
                               int total_out, int HW_in) {
    int idx = blockIdx.x * blockDim.x + threadIdx.x;
    if (idx >= total_out) return;
    int ho = HW_in >> 1;
    int xo = idx % ho;
    int yo = (idx / ho) % ho;
    int bo = idx / (ho * ho);
    const float* Xp = X + ((long)bo * HW_in + yo * 2) * HW_in + xo * 2;
    float m = fmaxf(fmaxf(Xp[0], Xp[1]), fmaxf(Xp[HW_in], Xp[HW_in + 1]));
    Y[idx] = m;
}

// ---------------- final linear: [256,512] @ [512,100]^T + b ---------------
__global__ void __launch_bounds__(128)
linear_kernel(const float* __restrict__ X,   // [256][512]
              const float* __restrict__ WT,  // [512][100]
              const float* __restrict__ bias,
              float* __restrict__ out) {     // [256][100]
    __shared__ float xs[4][512];
    int b0 = blockIdx.x * 4;
    for (int i = threadIdx.x; i < 4 * 512; i += blockDim.x)
        xs[i / 512][i % 512] = X[(long)b0 * 512 + i];
    __syncthreads();
    int o = threadIdx.x;
    if (o >= 100) return;
    float acc0 = 0.f, acc1 = 0.f, acc2 = 0.f, acc3 = 0.f;
    for (int k = 0; k < 512; k++) {
        float w = WT[k * 100 + o];
        acc0 = fmaf(xs[0][k], w, acc0);
        acc1 = fmaf(xs[1][k], w, acc1);
        acc2 = fmaf(xs[2][k], w, acc2);
        acc3 = fmaf(xs[3][k], w, acc3);
    }
    float bb = bias[o];
    out[(b0 + 0) * 100 + o] = acc0 + bb;
    out[(b0 + 1) * 100 + o] = acc1 + bb;
    out[(b0 + 2) * 100 + o] = acc2 + bb;
    out[(b0 + 3) * 100 + o] = acc3 + bb;
}

// ---------------- launch --------------------------------------------------
extern "C" void kernel_launch(void* const* d_in, const int* in_sizes, int n_in,
                              void* d_out, int out_size) {
    const float* x        = (const float*)d_in[0];
    const float* c1_bw    = (const float*)d_in[1];
    const float* c1_sw    = (const float*)d_in[2];
    const float* c1_sc    = (const float*)d_in[3];
    const float* c2_bw    = (const float*)d_in[4];
    const float* c2_sw    = (const float*)d_in[5];
    const float* c2_sc    = (const float*)d_in[6];
    const float* c3_bw    = (const float*)d_in[7];
    const float* c3_sw    = (const float*)d_in[8];
    const float* c3_sc    = (const float*)d_in[9];
    const float* lin_w    = (const float*)d_in[10];
    const float* lin_b    = (const float*)d_in[11];
    float* out = (float*)d_out;

    float *p_conv1, *p_pool1, *p_conv2, *p_pool2, *p_conv3, *p_pool3;
    float *p_sw1, *p_sw2, *p_sw3, *p_wt;
    cudaGetSymbolAddress((void**)&p_conv1, d_conv1);
    cudaGetSymbolAddress((void**)&p_pool1, d_pool1);
    cudaGetSymbolAddress((void**)&p_conv2, d_conv2);
    cudaGetSymbolAddress((void**)&p_pool2, d_pool2);
    cudaGetSymbolAddress((void**)&p_conv3, d_conv3);
    cudaGetSymbolAddress((void**)&p_pool3, d_pool3);
    cudaGetSymbolAddress((void**)&p_sw1,   d_sw1);
    cudaGetSymbolAddress((void**)&p_sw2,   d_sw2);
    cudaGetSymbolAddress((void**)&p_sw3,   d_sw3);
    cudaGetSymbolAddress((void**)&p_wt,    d_wt);

    // weight prep (cheap, included in the graph)
    prep_sw_kernel<<<(8  * 27  * 7 + 255) / 256, 256>>>(c1_bw, c1_sw, c1_sc, p_sw1, 8,  27);
    prep_sw_kernel<<<(16 * 72  * 7 + 255) / 256, 256>>>(c2_bw, c2_sw, c2_sc, p_sw2, 16, 72);
    prep_sw_kernel<<<(32 * 144 * 7 + 255) / 256, 256>>>(c3_bw, c3_sw, c3_sc, p_sw3, 32, 144);
    prep_wt_kernel<<<(100 * 512 + 255) / 256, 256>>>(lin_w, p_wt);

    // layer 1: [256,3,32,32] -> conv [256,8,32,32] -> pool [256,8,16,16]
    {
        dim3 grid(BATCH * 32 * 32 / 256, 1);
        conv_kan_kernel<3, 32, 1><<<grid, 256>>>(x, p_sw1, p_conv1);
        int n = BATCH * 8 * 16 * 16;
        maxpool_kernel<<<(n + 255) / 256, 256>>>(p_conv1, p_pool1, n, 32);
    }
    // layer 2: -> conv [256,16,16,16] -> pool [256,16,8,8]
    {
        dim3 grid(BATCH * 16 * 16 / 256, 2);
        conv_kan_kernel<8, 16, 2><<<grid, 256>>>(p_pool1, p_sw2, p_conv2);
        int n = BATCH * 16 * 8 * 8;
        maxpool_kernel<<<(n + 255) / 256, 256>>>(p_conv2, p_pool2, n, 16);
    }
    // layer 3: -> conv [256,32,8,8] -> pool [256,32,4,4]
    {
        dim3 grid(BATCH * 8 * 8 / 256, 4);
        conv_kan_kernel<16, 8, 4><<<grid, 256>>>(p_pool2, p_sw3, p_conv3);
        int n = BATCH * 32 * 4 * 4;
        maxpool_kernel<<<(n + 255) / 256, 256>>>(p_conv3, p_pool3, n, 8);
    }
    // linear: [256,512] @ [512,100] + b
    linear_kernel<<<BATCH / 4, 128>>>(p_pool3, p_wt, lin_b, out);
}

// round 3
// speedup vs baseline: 1.2361x; 1.2361x over previous
#include <cuda_runtime.h>
#include <cuda_bf16.h>

#define BATCH 256

// zero-value basis constants: v=0 -> t=4.5, i0=4, u=0.5
#define ZB2 (1.f/48.f)
#define ZB3 (23.f/48.f)

// ---------------- scratch (static device globals: allocation-free) ----------
// basis arrays padded to 8 floats/elem, spatial halo of 1 (P = HW+2)
__device__ float d_bas1 [BATCH * 3  * 34 * 34 * 8];
__device__ float d_conv1[BATCH * 8  * 32 * 32];
__device__ float d_bas2 [BATCH * 8  * 18 * 18 * 8];
__device__ float d_conv2[BATCH * 16 * 16 * 16];
__device__ float d_bas3 [BATCH * 16 * 10 * 10 * 8];
__device__ float d_conv3[BATCH * 32 * 8  * 8];
__device__ float d_pool3[BATCH * 32 * 4  * 4];
// combined weights: [n_otile][F][7 slots][8 ch], slot0=base_w, slots1..6=spline_w*scaler
__device__ float d_sw1[1 * 27  * 7 * 8];
__device__ float d_sw2[2 * 72  * 7 * 8];
__device__ float d_sw3[4 * 144 * 7 * 8];
__device__ float d_wt [512 * 100];   // transposed lin_w: [k][o]

// ---------------- basis evaluation (once per input element) ---------------
__device__ __forceinline__ void basis8(float v, float* sv) {
    sv[0] = v * (1.f / (1.f + __expf(-v)));          // silu
    float t  = (v + 3.f) * 1.5f;
    bool valid = (t >= 0.f) && (t < 9.f);
    float fi = floorf(t);
    int   i0 = (int)fi;
    float u  = t - fi;
    float u2 = u * u, u3 = u2 * u;
    float q3 = u3 * (1.f / 6.f);
    float q2 = ((3.f * u2 - 3.f * u3) + 3.f * u + 1.f) * (1.f / 6.f);
    float q1 = (3.f * u3 - 6.f * u2 + 4.f) * (1.f / 6.f);
    float iu = 1.f - u;
    float q0 = iu * iu * iu * (1.f / 6.f);
    if (!valid) { q0 = q1 = q2 = q3 = 0.f; i0 = -1000; }
#pragma unroll
    for (int m = 0; m < 6; m++) {
        int d = i0 - m;
        sv[1 + m] = (d == 0) ? q3 : (d == 1) ? q2 : (d == 2) ? q1
                  : (d == 3) ? q0 : 0.f;
    }
    sv[7] = 0.f;
}

__device__ __forceinline__ void store_bas(float* dst, const float* sv) {
    reinterpret_cast<float4*>(dst)[0] = make_float4(sv[0], sv[1], sv[2], sv[3]);
    reinterpret_cast<float4*>(dst)[1] = make_float4(sv[4], sv[5], sv[6], sv[7]);
}

// ---------------- layer-1 basis: x [B,C,HW,HW] -> bas [B,C,P,P,8] ----------
template<int C, int HW>
__global__ void basis_in_kernel(const float* __restrict__ X, float* __restrict__ BAS) {
    constexpr int P = HW + 2;
    int idx = blockIdx.x * blockDim.x + threadIdx.x;
    if (idx >= BATCH * C * P * P) return;
    int xp = idx % P;
    int yp = (idx / P) % P;
    int bc = idx / (P * P);
    float sv[8];
    if (xp == 0 || xp == P - 1 || yp == 0 || yp == P - 1) {
        sv[0] = 0.f; sv[1] = 0.f; sv[2] = ZB2; sv[3] = ZB3;
        sv[4] = ZB3; sv[5] = ZB2; sv[6] = 0.f; sv[7] = 0.f;
    } else {
        float v = X[((long)bc * HW + (yp - 1)) * HW + (xp - 1)];
        basis8(v, sv);
    }
    store_bas(BAS + (long)idx * 8, sv);
}

// ---------- fused maxpool(2x2) + basis: conv out -> next-layer basis -------
template<int C, int HWI>
__global__ void pool_basis_kernel(const float* __restrict__ X, float* __restrict__ BAS) {
    constexpr int HWO = HWI / 2;
    constexpr int P   = HWO + 2;
    int idx = blockIdx.x * blockDim.x + threadIdx.x;
    if (idx >= BATCH * C * P * P) return;
    int xp = idx % P;
    int yp = (idx / P) % P;
    int bc = idx / (P * P);
    float sv[8];
    if (xp == 0 || xp == P - 1 || yp == 0 || yp == P - 1) {
        sv[0] = 0.f; sv[1] = 0.f; sv[2] = ZB2; sv[3] = ZB3;
        sv[4] = ZB3; sv[5] = ZB2; sv[6] = 0.f; sv[7] = 0.f;
    } else {
        const float* Xp = X + ((long)bc * HWI + (yp - 1) * 2) * HWI + (xp - 1) * 2;
        float v = fmaxf(fmaxf(Xp[0], Xp[1]), fmaxf(Xp[HWI], Xp[HWI + 1]));
        basis8(v, sv);
    }
    store_bas(BAS + (long)idx * 8, sv);
}

// ---------------- fused KAN 3x3 conv over precomputed basis ----------------
// One thread = one conv output position x one tile of 8 output channels.
// Weight smem reads are warp-uniform (broadcast); basis reads are coalesced
// LDG.128 pairs; zero bounds checks thanks to the ZB halo.
template<int C, int HW, int NTILE>
__global__ void __launch_bounds__(256)
conv_kan_kernel(const float* __restrict__ BAS,   // [B][C][P][P][8]
                const float* __restrict__ SW,    // [NTILE][F][7][8]
                float* __restrict__ Y) {         // [B][NTILE*8][HW][HW]
    constexpr int F = C * 9;
    constexpr int O = NTILE * 8;
    constexpr int P = HW + 2;
    __shared__ float sw[F * 56];

    const float* gsw = SW + blockIdx.y * (F * 56);
    for (int i = threadIdx.x; i < F * 56 / 4; i += blockDim.x)
        reinterpret_cast<float4*>(sw)[i] = reinterpret_cast<const float4*>(gsw)[i];
    __syncthreads();

    int p = blockIdx.x * blockDim.x + threadIdx.x;
    if (p >= BATCH * HW * HW) return;
    int x = p % HW;
    int y = (p / HW) % HW;
    int b = p / (HW * HW);

    float acc[8];
#pragma unroll
    for (int j = 0; j < 8; j++) acc[j] = 0.f;

    const float* Bb = BAS + (long)b * C * P * P * 8;
    for (int c = 0; c < C; c++) {
        const float* Bc = Bb + c * P * P * 8;
#pragma unroll
        for (int ky = 0; ky < 3; ky++) {
#pragma unroll
            for (int kx = 0; kx < 3; kx++) {
                const float* bp = Bc + (((y + ky) * P) + (x + kx)) * 8;
                float4 s0 = *reinterpret_cast<const float4*>(bp);
                float4 s1 = *reinterpret_cast<const float4*>(bp + 4);
                const float* wp = sw + (c * 9 + ky * 3 + kx) * 56;
                float sv[7] = { s0.x, s0.y, s0.z, s0.w, s1.x, s1.y, s1.z };
#pragma unroll
                for (int s = 0; s < 7; s++) {
                    float4 wa = *reinterpret_cast<const float4*>(wp + s * 8);
                    float4 wb = *reinterpret_cast<const float4*>(wp + s * 8 + 4);
                    float sval = sv[s];
                    acc[0] = fmaf(sval, wa.x, acc[0]);
                    acc[1] = fmaf(sval, wa.y, acc[1]);
                    acc[2] = fmaf(sval, wa.z, acc[2]);
                    acc[3] = fmaf(sval, wa.w, acc[3]);
                    acc[4] = fmaf(sval, wb.x, acc[4]);
                    acc[5] = fmaf(sval, wb.y, acc[5]);
                    acc[6] = fmaf(sval, wb.z, acc[6]);
                    acc[7] = fmaf(sval, wb.w, acc[7]);
                }
            }
        }
    }

    float* Yp = Y + (((long)b * O + blockIdx.y * 8) * HW + y) * HW + x;
#pragma unroll
    for (int j = 0; j < 8; j++) Yp[j * HW * HW] = acc[j];
}

// ---------------- plain 2x2 maxpool (final layer only) --------------------
__global__ void maxpool_kernel(const float* __restrict__ X, float* __restrict__ Y,
                               int total_out, int HW_in) {
    int idx = blockIdx.x * blockDim.x + threadIdx.x;
    if (idx >= total_out) return;
    int ho = HW_in >> 1;
    int xo = idx % ho;
    int yo = (idx / ho) % ho;
    int bo = idx / (ho * ho);
    const float* Xp = X + ((long)bo * HW_in + yo * 2) * HW_in + xo * 2;
    Y[idx] = fmaxf(fmaxf(Xp[0], Xp[1]), fmaxf(Xp[HW_in], Xp[HW_in + 1]));
}

// ---------------- weight prep ---------------------------------------------
__global__ void prep_sw_kernel(const float* __restrict__ base_w,
                               const float* __restrict__ spline_w,
                               const float* __restrict__ scaler,
                               float* __restrict__ sw, int O, int F) {
    int idx = blockIdx.x * blockDim.x + threadIdx.x;
    if (idx >= O * F * 7) return;
    int slot = idx % 7;
    int f    = (idx / 7) % F;
    int o    = idx / (7 * F);
    float v;
    if (slot == 0) v = base_w[o * F + f];
    else           v = spline_w[(o * F + f) * 6 + (slot - 1)] * scaler[o * F + f];
    int tile = o >> 3, j = o & 7;
    sw[((tile * F + f) * 7 + slot) * 8 + j] = v;
}

__global__ void prep_wt_kernel(const float* __restrict__ w, float* __restrict__ wt) {
    int idx = blockIdx.x * blockDim.x + threadIdx.x;   // 100*512
    if (idx >= 100 * 512) return;
    int o = idx / 512, k = idx % 512;
    wt[k * 100 + o] = w[idx];
}

// ---------------- final linear: [256,512] @ [512,100]^T + b ----------------
__global__ void __launch_bounds__(128)
linear_kernel(const float* __restrict__ X, const float* __restrict__ WT,
              const float* __restrict__ bias, float* __restrict__ out) {
    __shared__ float xs[4][512];
    int b0 = blockIdx.x * 4;
    for (int i = threadIdx.x; i < 4 * 512; i += blockDim.x)
        xs[i / 512][i % 512] = X[(long)b0 * 512 + i];
    __syncthreads();
    int o = threadIdx.x;
    if (o >= 100) return;
    float acc0 = 0.f, acc1 = 0.f, acc2 = 0.f, acc3 = 0.f;
    for (int k = 0; k < 512; k++) {
        float w = WT[k * 100 + o];
        acc0 = fmaf(xs[0][k], w, acc0);
        acc1 = fmaf(xs[1][k], w, acc1);
        acc2 = fmaf(xs[2][k], w, acc2);
        acc3 = fmaf(xs[3][k], w, acc3);
    }
    float bb = bias[o];
    out[(b0 + 0) * 100 + o] = acc0 + bb;
    out[(b0 + 1) * 100 + o] = acc1 + bb;
    out[(b0 + 2) * 100 + o] = acc2 + bb;
    out[(b0 + 3) * 100 + o] = acc3 + bb;
}

// ---------------- launch ---------------------------------------------------
extern "C" void kernel_launch(void* const* d_in, const int* in_sizes, int n_in,
                              void* d_out, int out_size) {
    const float* x     = (const float*)d_in[0];
    const float* c1_bw = (const float*)d_in[1];
    const float* c1_sw = (const float*)d_in[2];
    const float* c1_sc = (const float*)d_in[3];
    const float* c2_bw = (const float*)d_in[4];
    const float* c2_sw = (const float*)d_in[5];
    const float* c2_sc = (const float*)d_in[6];
    const float* c3_bw = (const float*)d_in[7];
    const float* c3_sw = (const float*)d_in[8];
    const float* c3_sc = (const float*)d_in[9];
    const float* lin_w = (const float*)d_in[10];
    const float* lin_b = (const float*)d_in[11];
    float* out = (float*)d_out;

    float *p_bas1, *p_conv1, *p_bas2, *p_conv2, *p_bas3, *p_conv3, *p_pool3;
    float *p_sw1, *p_sw2, *p_sw3, *p_wt;
    cudaGetSymbolAddress((void**)&p_bas1,  d_bas1);
    cudaGetSymbolAddress((void**)&p_conv1, d_conv1);
    cudaGetSymbolAddress((void**)&p_bas2,  d_bas2);
    cudaGetSymbolAddress((void**)&p_conv2, d_conv2);
    cudaGetSymbolAddress((void**)&p_bas3,  d_bas3);
    cudaGetSymbolAddress((void**)&p_conv3, d_conv3);
    cudaGetSymbolAddress((void**)&p_pool3, d_pool3);
    cudaGetSymbolAddress((void**)&p_sw1,   d_sw1);
    cudaGetSymbolAddress((void**)&p_sw2,   d_sw2);
    cudaGetSymbolAddress((void**)&p_sw3,   d_sw3);
    cudaGetSymbolAddress((void**)&p_wt,    d_wt);

    // weight prep
    prep_sw_kernel<<<(8  * 27  * 7 + 255) / 256, 256>>>(c1_bw, c1_sw, c1_sc, p_sw1, 8,  27);
    prep_sw_kernel<<<(16 * 72  * 7 + 255) / 256, 256>>>(c2_bw, c2_sw, c2_sc, p_sw2, 16, 72);
    prep_sw_kernel<<<(32 * 144 * 7 + 255) / 256, 256>>>(c3_bw, c3_sw, c3_sc, p_sw3, 32, 144);
    prep_wt_kernel<<<(100 * 512 + 255) / 256, 256>>>(lin_w, p_wt);

    // layer 1
    {
        int n = BATCH * 3 * 34 * 34;
        basis_in_kernel<3, 32><<<(n + 255) / 256, 256>>>(x, p_bas1);
        dim3 grid(BATCH * 32 * 32 / 256, 1);
        conv_kan_kernel<3, 32, 1><<<grid, 256>>>(p_bas1, p_sw1, p_conv1);
        int m = BATCH * 8 * 18 * 18;
        pool_basis_kernel<8, 32><<<(m + 255) / 256, 256>>>(p_conv1, p_bas2);
    }
    // layer 2
    {
        dim3 grid(BATCH * 16 * 16 / 256, 2);
        conv_kan_kernel<8, 16, 2><<<grid, 256>>>(p_bas2, p_sw2, p_conv2);
        int m = BATCH * 16 * 10 * 10;
        pool_basis_kernel<16, 16><<<(m + 255) / 256, 256>>>(p_conv2, p_bas3);
    }
    // layer 3
    {
        dim3 grid(BATCH * 8 * 8 / 256, 4);
        conv_kan_kernel<16, 8, 4><<<grid, 256>>>(p_bas3, p_sw3, p_conv3);
        int n = BATCH * 32 * 4 * 4;
        maxpool_kernel<<<(n + 255) / 256, 256>>>(p_conv3, p_pool3, n, 8);
    }
    // linear
    linear_kernel<<<BATCH / 4, 128>>>(p_pool3, p_wt, lin_b, out);
}

// round 6
// speedup vs baseline: 1.4389x; 1.1641x over previous
#include <cuda_runtime.h>
#include <cuda_bf16.h>

#define BATCH 256

// zero-value basis constants: v=0 -> t=4.5, i0=4, u=0.5
#define ZB2 (1.f/48.f)
#define ZB3 (23.f/48.f)

// ---------------- scratch (static device globals: allocation-free) ----------
__device__ float d_bas1 [BATCH * 3  * 34 * 34 * 8];
__device__ float d_conv1[BATCH * 8  * 32 * 32];
__device__ float d_bas2 [BATCH * 8  * 18 * 18 * 8];
__device__ float d_conv2[BATCH * 16 * 16 * 16];
__device__ float d_bas3 [BATCH * 16 * 10 * 10 * 8];
__device__ float d_conv3[BATCH * 32 * 8  * 8];
__device__ float d_pool3[BATCH * 32 * 4  * 4];
// combined weights: [n_otile][F][7 slots][8 ch], slot0=base_w, slots1..6=spline_w*scaler
__device__ float d_sw1[1 * 27  * 7 * 8];
__device__ float d_sw2[2 * 72  * 7 * 8];
__device__ float d_sw3[4 * 144 * 7 * 8];
__device__ float d_wt [512 * 100];   // transposed lin_w: [k][o]

// ---------------- basis evaluation (once per input element) ---------------
__device__ __forceinline__ void basis8(float v, float* sv) {
    sv[0] = v * (1.f / (1.f + __expf(-v)));          // silu
    float t  = (v + 3.f) * 1.5f;
    bool valid = (t >= 0.f) && (t < 9.f);
    float fi = floorf(t);
    int   i0 = (int)fi;
    float u  = t - fi;
    float u2 = u * u, u3 = u2 * u;
    float q3 = u3 * (1.f / 6.f);
    float q2 = ((3.f * u2 - 3.f * u3) + 3.f * u + 1.f) * (1.f / 6.f);
    float q1 = (3.f * u3 - 6.f * u2 + 4.f) * (1.f / 6.f);
    float iu = 1.f - u;
    float q0 = iu * iu * iu * (1.f / 6.f);
    if (!valid) { q0 = q1 = q2 = q3 = 0.f; i0 = -1000; }
#pragma unroll
    for (int m = 0; m < 6; m++) {
        int d = i0 - m;
        sv[1 + m] = (d == 0) ? q3 : (d == 1) ? q2 : (d == 2) ? q1
                  : (d == 3) ? q0 : 0.f;
    }
    sv[7] = 0.f;
}

__device__ __forceinline__ void store_bas(float* dst, const float* sv) {
    reinterpret_cast<float4*>(dst)[0] = make_float4(sv[0], sv[1], sv[2], sv[3]);
    reinterpret_cast<float4*>(dst)[1] = make_float4(sv[4], sv[5], sv[6], sv[7]);
}

// ---------------- layer-1 basis: x [B,C,HW,HW] -> bas [B,C,P,P,8] ----------
template<int C, int HW>
__global__ void basis_in_kernel(const float* __restrict__ X, float* __restrict__ BAS) {
    constexpr int P = HW + 2;
    int idx = blockIdx.x * blockDim.x + threadIdx.x;
    if (idx >= BATCH * C * P * P) return;
    int xp = idx % P;
    int yp = (idx / P) % P;
    int bc = idx / (P * P);
    float sv[8];
    if (xp == 0 || xp == P - 1 || yp == 0 || yp == P - 1) {
        sv[0] = 0.f; sv[1] = 0.f; sv[2] = ZB2; sv[3] = ZB3;
        sv[4] = ZB3; sv[5] = ZB2; sv[6] = 0.f; sv[7] = 0.f;
    } else {
        float v = X[((long)bc * HW + (yp - 1)) * HW + (xp - 1)];
        basis8(v, sv);
    }
    store_bas(BAS + (long)idx * 8, sv);
}

// ---------- fused maxpool(2x2) + basis: conv out -> next-layer basis -------
template<int C, int HWI>
__global__ void pool_basis_kernel(const float* __restrict__ X, float* __restrict__ BAS) {
    constexpr int HWO = HWI / 2;
    constexpr int P   = HWO + 2;
    int idx = blockIdx.x * blockDim.x + threadIdx.x;
    if (idx >= BATCH * C * P * P) return;
    int xp = idx % P;
    int yp = (idx / P) % P;
    int bc = idx / (P * P);
    float sv[8];
    if (xp == 0 || xp == P - 1 || yp == 0 || yp == P - 1) {
        sv[0] = 0.f; sv[1] = 0.f; sv[2] = ZB2; sv[3] = ZB3;
        sv[4] = ZB3; sv[5] = ZB2; sv[6] = 0.f; sv[7] = 0.f;
    } else {
        const float* Xp = X + ((long)bc * HWI + (yp - 1) * 2) * HWI + (xp - 1) * 2;
        float v = fmaxf(fmaxf(Xp[0], Xp[1]), fmaxf(Xp[HWI], Xp[HWI + 1]));
        basis8(v, sv);
    }
    store_bas(BAS + (long)idx * 8, sv);
}

// ---------------- fused KAN 3x3 conv over precomputed basis ----------------
// One thread = TWO adjacent x positions x one tile of 8 output channels.
// Per (c,ky): 8 batched LDG.128 (4 basis vecs serve 6 tap-instances);
// each weight LDS.128 pair feeds 16 FMAs. Zero bounds checks (ZB halo).
template<int C, int HW, int NTILE>
__global__ void __launch_bounds__(256)
conv_kan_kernel(const float* __restrict__ BAS,   // [B][C][P][P][8]
                const float* __restrict__ SW,    // [NTILE][F][7][8]
                float* __restrict__ Y) {         // [B][NTILE*8][HW][HW]
    constexpr int F  = C * 9;
    constexpr int O  = NTILE * 8;
    constexpr int P  = HW + 2;
    constexpr int HX = HW / 2;
    __shared__ float sw[F * 56];

    const float* gsw = SW + blockIdx.y * (F * 56);
    for (int i = threadIdx.x; i < F * 56 / 4; i += blockDim.x)
        reinterpret_cast<float4*>(sw)[i] = reinterpret_cast<const float4*>(gsw)[i];
    __syncthreads();

    int p = blockIdx.x * blockDim.x + threadIdx.x;
    if (p >= BATCH * HW * HX) return;
    int x0 = (p % HX) * 2;
    int y  = (p / HX) % HW;
    int b  = p / (HX * HW);

    float acc[16];              // [pos0 ch0..7 | pos1 ch0..7]
#pragma unroll
    for (int j = 0; j < 16; j++) acc[j] = 0.f;

    const float* Bb = BAS + (long)b * C * P * P * 8;
    for (int c = 0; c < C; c++) {
        const float* Bc = Bb + c * P * P * 8;
#pragma unroll
        for (int ky = 0; ky < 3; ky++) {
            const float* rp = Bc + (((y + ky) * P) + x0) * 8;
            float bvf[4][8];    // basis vecs for padded x0..x0+3
#pragma unroll
            for (int i = 0; i < 4; i++) {
                float4 t0 = *reinterpret_cast<const float4*>(rp + i * 8);
                float4 t1 = *reinterpret_cast<const float4*>(rp + i * 8 + 4);
                bvf[i][0] = t0.x; bvf[i][1] = t0.y; bvf[i][2] = t0.z; bvf[i][3] = t0.w;
                bvf[i][4] = t1.x; bvf[i][5] = t1.y; bvf[i][6] = t1.z; bvf[i][7] = t1.w;
            }
            const float* wbase = sw + (c * 9 + ky * 3) * 56;
#pragma unroll
            for (int kx = 0; kx < 3; kx++) {
                const float* wp = wbase + kx * 56;
#pragma unroll
                for (int s = 0; s < 7; s++) {
                    float4 wa = *reinterpret_cast<const float4*>(wp + s * 8);
                    float4 wb = *reinterpret_cast<const float4*>(wp + s * 8 + 4);
                    float s0 = bvf[kx][s];
                    float s1 = bvf[kx + 1][s];
                    acc[0]  = fmaf(s0, wa.x, acc[0]);
                    acc[1]  = fmaf(s0, wa.y, acc[1]);
                    acc[2]  = fmaf(s0, wa.z, acc[2]);
                    acc[3]  = fmaf(s0, wa.w, acc[3]);
                    acc[4]  = fmaf(s0, wb.x, acc[4]);
                    acc[5]  = fmaf(s0, wb.y, acc[5]);
                    acc[6]  = fmaf(s0, wb.z, acc[6]);
                    acc[7]  = fmaf(s0, wb.w, acc[7]);
                    acc[8]  = fmaf(s1, wa.x, acc[8]);
                    acc[9]  = fmaf(s1, wa.y, acc[9]);
                    acc[10] = fmaf(s1, wa.z, acc[10]);
                    acc[11] = fmaf(s1, wa.w, acc[11]);
                    acc[12] = fmaf(s1, wb.x, acc[12]);
                    acc[13] = fmaf(s1, wb.y, acc[13]);
                    acc[14] = fmaf(s1, wb.z, acc[14]);
                    acc[15] = fmaf(s1, wb.w, acc[15]);
                }
            }
        }
    }

    float* Yp = Y + (((long)b * O + blockIdx.y * 8) * HW + y) * HW + x0;
#pragma unroll
    for (int j = 0; j < 8; j++)
        *reinterpret_cast<float2*>(Yp + j * HW * HW) = make_float2(acc[j], acc[8 + j]);
}

// ---------------- plain 2x2 maxpool (final layer only) --------------------
__global__ void maxpool_kernel(const float* __restrict__ X, float* __restrict__ Y,
                               int total_out, int HW_in) {
    int idx = blockIdx.x * blockDim.x + threadIdx.x;
    if (idx >= total_out) return;
    int ho = HW_in >> 1;
    int xo = idx % ho;
    int yo = (idx / ho) % ho;
    int bo = idx / (ho * ho);
    const float* Xp = X + ((long)bo * HW_in + yo * 2) * HW_in + xo * 2;
    Y[idx] = fmaxf(fmaxf(Xp[0], Xp[1]), fmaxf(Xp[HW_in], Xp[HW_in + 1]));
}

// ---------------- merged weight prep --------------------------------------
__device__ __forceinline__ void prep_sw_elem(const float* base_w, const float* spline_w,
                                             const float* scaler, float* sw,
                                             int idx, int F) {
    int slot = idx % 7;
    int f    = (idx / 7) % F;
    int o    = idx / (7 * F);
    float v;
    if (slot == 0) v = base_w[o * F + f];
    else           v = spline_w[(o * F + f) * 6 + (slot - 1)] * scaler[o * F + f];
    int tile = o >> 3, j = o & 7;
    sw[((tile * F + f) * 7 + slot) * 8 + j] = v;
}

__global__ void prep_all_kernel(const float* __restrict__ c1_bw, const float* __restrict__ c1_sw,
                                const float* __restrict__ c1_sc,
                                const float* __restrict__ c2_bw, const float* __restrict__ c2_sw,
                                const float* __restrict__ c2_sc,
                                const float* __restrict__ c3_bw, const float* __restrict__ c3_sw,
                                const float* __restrict__ c3_sc,
                                const float* __restrict__ lin_w,
                                float* __restrict__ sw1, float* __restrict__ sw2,
                                float* __restrict__ sw3, float* __restrict__ wt) {
    const int N1 = 8 * 27 * 7, N2 = 16 * 72 * 7, N3 = 32 * 144 * 7, NW = 100 * 512;
    int idx = blockIdx.x * blockDim.x + threadIdx.x;
    if (idx < N1)                    prep_sw_elem(c1_bw, c1_sw, c1_sc, sw1, idx, 27);
    else if (idx < N1 + N2)          prep_sw_elem(c2_bw, c2_sw, c2_sc, sw2, idx - N1, 72);
    else if (idx < N1 + N2 + N3)     prep_sw_elem(c3_bw, c3_sw, c3_sc, sw3, idx - N1 - N2, 144);
    else if (idx < N1 + N2 + N3 + NW) {
        int i = idx - N1 - N2 - N3;
        int o = i / 512, k = i % 512;
        wt[k * 100 + o] = lin_w[i];
    }
}

// ---------------- final linear: [256,512] @ [512,100]^T + b ----------------
__global__ void __launch_bounds__(128)
linear_kernel(const float* __restrict__ X, const float* __restrict__ WT,
              const float* __restrict__ bias, float* __restrict__ out) {
    __shared__ float xs[4][512];
    int b0 = blockIdx.x * 4;
    for (int i = threadIdx.x; i < 4 * 512; i += blockDim.x)
        xs[i / 512][i % 512] = X[(long)b0 * 512 + i];
    __syncthreads();
    int o = threadIdx.x;
    if (o >= 100) return;
    float acc0 = 0.f, acc1 = 0.f, acc2 = 0.f, acc3 = 0.f;
    for (int k = 0; k < 512; k++) {
        float w = WT[k * 100 + o];
        acc0 = fmaf(xs[0][k], w, acc0);
        acc1 = fmaf(xs[1][k], w, acc1);
        acc2 = fmaf(xs[2][k], w, acc2);
        acc3 = fmaf(xs[3][k], w, acc3);
    }
    float bb = bias[o];
    out[(b0 + 0) * 100 + o] = acc0 + bb;
    out[(b0 + 1) * 100 + o] = acc1 + bb;
    out[(b0 + 2) * 100 + o] = acc2 + bb;
    out[(b0 + 3) * 100 + o] = acc3 + bb;
}

// ---------------- launch ---------------------------------------------------
extern "C" void kernel_launch(void* const* d_in, const int* in_sizes, int n_in,
                              void* d_out, int out_size) {
    const float* x     = (const float*)d_in[0];
    const float* c1_bw = (const float*)d_in[1];
    const float* c1_sw = (const float*)d_in[2];
    const float* c1_sc = (const float*)d_in[3];
    const float* c2_bw = (const float*)d_in[4];
    const float* c2_sw = (const float*)d_in[5];
    const float* c2_sc = (const float*)d_in[6];
    const float* c3_bw = (const float*)d_in[7];
    const float* c3_sw = (const float*)d_in[8];
    const float* c3_sc = (const float*)d_in[9];
    const float* lin_w = (const float*)d_in[10];
    const float* lin_b = (const float*)d_in[11];
    float* out = (float*)d_out;

    float *p_bas1, *p_conv1, *p_bas2, *p_conv2, *p_bas3, *p_conv3, *p_pool3;
    float *p_sw1, *p_sw2, *p_sw3, *p_wt;
    cudaGetSymbolAddress((void**)&p_bas1,  d_bas1);
    cudaGetSymbolAddress((void**)&p_conv1, d_conv1);
    cudaGetSymbolAddress((void**)&p_bas2,  d_bas2);
    cudaGetSymbolAddress((void**)&p_conv2, d_conv2);
    cudaGetSymbolAddress((void**)&p_bas3,  d_bas3);
    cudaGetSymbolAddress((void**)&p_conv3, d_conv3);
    cudaGetSymbolAddress((void**)&p_pool3, d_pool3);
    cudaGetSymbolAddress((void**)&p_sw1,   d_sw1);
    cudaGetSymbolAddress((void**)&p_sw2,   d_sw2);
    cudaGetSymbolAddress((void**)&p_sw3,   d_sw3);
    cudaGetSymbolAddress((void**)&p_wt,    d_wt);

    // merged weight prep (1 launch)
    {
        int total = 8*27*7 + 16*72*7 + 32*144*7 + 100*512;
        prep_all_kernel<<<(total + 255) / 256, 256>>>(
            c1_bw, c1_sw, c1_sc, c2_bw, c2_sw, c2_sc, c3_bw, c3_sw, c3_sc,
            lin_w, p_sw1, p_sw2, p_sw3, p_wt);
    }
    // layer 1
    {
        int n = BATCH * 3 * 34 * 34;
        basis_in_kernel<3, 32><<<(n + 255) / 256, 256>>>(x, p_bas1);
        dim3 grid(BATCH * 32 * 16 / 256, 1);
        conv_kan_kernel<3, 32, 1><<<grid, 256>>>(p_bas1, p_sw1, p_conv1);
        int m = BATCH * 8 * 18 * 18;
        pool_basis_kernel<8, 32><<<(m + 255) / 256, 256>>>(p_conv1, p_bas2);
    }
    // layer 2
    {
        dim3 grid(BATCH * 16 * 8 / 256, 2);
        conv_kan_kernel<8, 16, 2><<<grid, 256>>>(p_bas2, p_sw2, p_conv2);
        int m = BATCH * 16 * 10 * 10;
        pool_basis_kernel<16, 16><<<(m + 255) / 256, 256>>>(p_conv2, p_bas3);
    }
    // layer 3
    {
        dim3 grid(BATCH * 8 * 4 / 256, 4);
        conv_kan_kernel<16, 8, 4><<<grid, 256>>>(p_bas3, p_sw3, p_conv3);
        int n = BATCH * 32 * 4 * 4;
        maxpool_kernel<<<(n + 255) / 256, 256>>>(p_conv3, p_pool3, n, 8);
    }
    // linear
    linear_kernel<<<BATCH / 4, 128>>>(p_pool3, p_wt, lin_b, out);
}

// round 7
// speedup vs baseline: 1.4412x; 1.0016x over previous
#include <cuda_runtime.h>
#include <cuda_bf16.h>

#define BATCH 256

// zero-value basis constants: v=0 -> t=4.5, i0=4, u=0.5
#define ZB2 (1.f/48.f)
#define ZB3 (23.f/48.f)

typedef unsigned long long u64;

// ---------------- packed f32x2 helpers (Blackwell FFMA2) -------------------
__device__ __forceinline__ u64 pack2(float x, float y) {
    u64 r; asm("mov.b64 %0, {%1, %2};" : "=l"(r) : "f"(x), "f"(y)); return r;
}
__device__ __forceinline__ u64 pack_dup(float x) {
    u64 r; asm("mov.b64 %0, {%1, %1};" : "=l"(r) : "f"(x)); return r;
}
__device__ __forceinline__ void unpack2(u64 v, float& x, float& y) {
    asm("mov.b64 {%0, %1}, %2;" : "=f"(x), "=f"(y) : "l"(v));
}
__device__ __forceinline__ void ffma2(u64& d, u64 a, u64 b) {
    asm("fma.rn.f32x2 %0, %1, %2, %0;" : "+l"(d) : "l"(a), "l"(b));
}

// ---------------- scratch (static device globals: allocation-free) ----------
__device__ float d_bas1 [BATCH * 3  * 34 * 34 * 8];
__device__ float d_conv1[BATCH * 8  * 32 * 32];
__device__ float d_bas2 [BATCH * 8  * 18 * 18 * 8];
__device__ float d_conv2[BATCH * 16 * 16 * 16];
__device__ float d_bas3 [BATCH * 16 * 10 * 10 * 8];
__device__ float d_conv3[BATCH * 32 * 8  * 8];
__device__ float d_pool3[BATCH * 32 * 4  * 4];
// combined weights: [n_otile][F][7 slots][8 ch], slot0=base_w, slots1..6=spline_w*scaler
__device__ float d_sw1[1 * 27  * 7 * 8];
__device__ float d_sw2[2 * 72  * 7 * 8];
__device__ float d_sw3[4 * 144 * 7 * 8];
__device__ float d_wt [512 * 100];   // transposed lin_w: [k][o]

// ---------------- basis evaluation (once per input element) ---------------
__device__ __forceinline__ void basis8(float v, float* sv) {
    sv[0] = v * (1.f / (1.f + __expf(-v)));          // silu
    float t  = (v + 3.f) * 1.5f;
    bool valid = (t >= 0.f) && (t < 9.f);
    float fi = floorf(t);
    int   i0 = (int)fi;
    float u  = t - fi;
    float u2 = u * u, u3 = u2 * u;
    float q3 = u3 * (1.f / 6.f);
    float q2 = ((3.f * u2 - 3.f * u3) + 3.f * u + 1.f) * (1.f / 6.f);
    float q1 = (3.f * u3 - 6.f * u2 + 4.f) * (1.f / 6.f);
    float iu = 1.f - u;
    float q0 = iu * iu * iu * (1.f / 6.f);
    if (!valid) { q0 = q1 = q2 = q3 = 0.f; i0 = -1000; }
#pragma unroll
    for (int m = 0; m < 6; m++) {
        int d = i0 - m;
        sv[1 + m] = (d == 0) ? q3 : (d == 1) ? q2 : (d == 2) ? q1
                  : (d == 3) ? q0 : 0.f;
    }
    sv[7] = 0.f;
}

__device__ __forceinline__ void store_bas(float* dst, const float* sv) {
    reinterpret_cast<float4*>(dst)[0] = make_float4(sv[0], sv[1], sv[2], sv[3]);
    reinterpret_cast<float4*>(dst)[1] = make_float4(sv[4], sv[5], sv[6], sv[7]);
}

// ---------------- layer-1 basis: x [B,C,HW,HW] -> bas [B,C,P,P,8] ----------
template<int C, int HW>
__global__ void basis_in_kernel(const float* __restrict__ X, float* __restrict__ BAS) {
    constexpr int P = HW + 2;
    int idx = blockIdx.x * blockDim.x + threadIdx.x;
    if (idx >= BATCH * C * P * P) return;
    int xp = idx % P;
    int yp = (idx / P) % P;
    int bc = idx / (P * P);
    float sv[8];
    if (xp == 0 || xp == P - 1 || yp == 0 || yp == P - 1) {
        sv[0] = 0.f; sv[1] = 0.f; sv[2] = ZB2; sv[3] = ZB3;
        sv[4] = ZB3; sv[5] = ZB2; sv[6] = 0.f; sv[7] = 0.f;
    } else {
        float v = X[((long)bc * HW + (yp - 1)) * HW + (xp - 1)];
        basis8(v, sv);
    }
    store_bas(BAS + (long)idx * 8, sv);
}

// ---------- fused maxpool(2x2) + basis: conv out -> next-layer basis -------
template<int C, int HWI>
__global__ void pool_basis_kernel(const float* __restrict__ X, float* __restrict__ BAS) {
    constexpr int HWO = HWI / 2;
    constexpr int P   = HWO + 2;
    int idx = blockIdx.x * blockDim.x + threadIdx.x;
    if (idx >= BATCH * C * P * P) return;
    int xp = idx % P;
    int yp = (idx / P) % P;
    int bc = idx / (P * P);
    float sv[8];
    if (xp == 0 || xp == P - 1 || yp == 0 || yp == P - 1) {
        sv[0] = 0.f; sv[1] = 0.f; sv[2] = ZB2; sv[3] = ZB3;
        sv[4] = ZB3; sv[5] = ZB2; sv[6] = 0.f; sv[7] = 0.f;
    } else {
        const float* Xp = X + ((long)bc * HWI + (yp - 1) * 2) * HWI + (xp - 1) * 2;
        float v = fmaxf(fmaxf(Xp[0], Xp[1]), fmaxf(Xp[HWI], Xp[HWI + 1]));
        basis8(v, sv);
    }
    store_bas(BAS + (long)idx * 8, sv);
}

// ---------------- fused KAN 3x3 conv over precomputed basis ----------------
// One thread = TWO adjacent x positions x one tile of 8 output channels.
// Channel pairs accumulated in packed f32x2 registers -> FFMA2 (half the
// fma-pipe issue slots). Weight smem reads are broadcast LDS.128 as
// ulonglong2; basis reads batched LDG.128; zero bounds checks (ZB halo).
template<int C, int HW, int NTILE>
__global__ void __launch_bounds__(128)
conv_kan_kernel(const float* __restrict__ BAS,   // [B][C][P][P][8]
                const float* __restrict__ SW,    // [NTILE][F][7][8]
                float* __restrict__ Y) {         // [B][NTILE*8][HW][HW]
    constexpr int F  = C * 9;
    constexpr int O  = NTILE * 8;
    constexpr int P  = HW + 2;
    constexpr int HX = HW / 2;
    __shared__ float sw[F * 56];

    const float* gsw = SW + blockIdx.y * (F * 56);
    for (int i = threadIdx.x; i < F * 56 / 4; i += blockDim.x)
        reinterpret_cast<float4*>(sw)[i] = reinterpret_cast<const float4*>(gsw)[i];
    __syncthreads();

    int p = blockIdx.x * blockDim.x + threadIdx.x;
    if (p >= BATCH * HW * HX) return;
    int x0 = (p % HX) * 2;
    int y  = (p / HX) % HW;
    int b  = p / (HX * HW);

    // acc2[0..3] = pos0 channel pairs (01,23,45,67); acc2[4..7] = pos1
    u64 acc2[8];
#pragma unroll
    for (int j = 0; j < 8; j++) acc2[j] = 0ull;

    const float* Bb = BAS + (long)b * C * P * P * 8;
    for (int c = 0; c < C; c++) {
        const float* Bc = Bb + c * P * P * 8;
#pragma unroll
        for (int ky = 0; ky < 3; ky++) {
            const float* rp = Bc + (((y + ky) * P) + x0) * 8;
            float bvf[4][8];    // basis vecs for padded x0..x0+3
#pragma unroll
            for (int i = 0; i < 4; i++) {
                float4 t0 = *reinterpret_cast<const float4*>(rp + i * 8);
                float4 t1 = *reinterpret_cast<const float4*>(rp + i * 8 + 4);
                bvf[i][0] = t0.x; bvf[i][1] = t0.y; bvf[i][2] = t0.z; bvf[i][3] = t0.w;
                bvf[i][4] = t1.x; bvf[i][5] = t1.y; bvf[i][6] = t1.z; bvf[i][7] = t1.w;
            }
            const float* wbase = sw + (c * 9 + ky * 3) * 56;
#pragma unroll
            for (int kx = 0; kx < 3; kx++) {
                const float* wp = wbase + kx * 56;
#pragma unroll
                for (int s = 0; s < 7; s++) {
                    ulonglong2 w01 = *reinterpret_cast<const ulonglong2*>(wp + s * 8);
                    ulonglong2 w23 = *reinterpret_cast<const ulonglong2*>(wp + s * 8 + 4);
                    u64 sp0 = pack_dup(bvf[kx][s]);
                    u64 sp1 = pack_dup(bvf[kx + 1][s]);
                    ffma2(acc2[0], sp0, w01.x);
                    ffma2(acc2[1], sp0, w01.y);
                    ffma2(acc2[2], sp0, w23.x);
                    ffma2(acc2[3], sp0, w23.y);
                    ffma2(acc2[4], sp1, w01.x);
                    ffma2(acc2[5], sp1, w01.y);
                    ffma2(acc2[6], sp1, w23.x);
                    ffma2(acc2[7], sp1, w23.y);
                }
            }
        }
    }

    // unpack: acc2[q] = {ch2q, ch2q+1} for pos0 (q<4) / pos1 (q>=4)
    float a0[8], a1[8];
#pragma unroll
    for (int q = 0; q < 4; q++) {
        unpack2(acc2[q],     a0[2 * q], a0[2 * q + 1]);
        unpack2(acc2[4 + q], a1[2 * q], a1[2 * q + 1]);
    }
    float* Yp = Y + (((long)b * O + blockIdx.y * 8) * HW + y) * HW + x0;
#pragma unroll
    for (int j = 0; j < 8; j++)
        *reinterpret_cast<float2*>(Yp + j * HW * HW) = make_float2(a0[j], a1[j]);
}

// ---------------- plain 2x2 maxpool (final layer only) --------------------
__global__ void maxpool_kernel(const float* __restrict__ X, float* __restrict__ Y,
                               int total_out, int HW_in) {
    int idx = blockIdx.x * blockDim.x + threadIdx.x;
    if (idx >= total_out) return;
    int ho = HW_in >> 1;
    int xo = idx % ho;
    int yo = (idx / ho) % ho;
    int bo = idx / (ho * ho);
    const float* Xp = X + ((long)bo * HW_in + yo * 2) * HW_in + xo * 2;
    Y[idx] = fmaxf(fmaxf(Xp[0], Xp[1]), fmaxf(Xp[HW_in], Xp[HW_in + 1]));
}

// ---------------- merged weight prep --------------------------------------
__device__ __forceinline__ void prep_sw_elem(const float* base_w, const float* spline_w,
                                             const float* scaler, float* sw,
                                             int idx, int F) {
    int slot = idx % 7;
    int f    = (idx / 7) % F;
    int o    = idx / (7 * F);
    float v;
    if (slot == 0) v = base_w[o * F + f];
    else           v = spline_w[(o * F + f) * 6 + (slot - 1)] * scaler[o * F + f];
    int tile = o >> 3, j = o & 7;
    sw[((tile * F + f) * 7 + slot) * 8 + j] = v;
}

__global__ void prep_all_kernel(const float* __restrict__ c1_bw, const float* __restrict__ c1_sw,
                                const float* __restrict__ c1_sc,
                                const float* __restrict__ c2_bw, const float* __restrict__ c2_sw,
                                const float* __restrict__ c2_sc,
                                const float* __restrict__ c3_bw, const float* __restrict__ c3_sw,
                                const float* __restrict__ c3_sc,
                                const float* __restrict__ lin_w,
                                float* __restrict__ sw1, float* __restrict__ sw2,
                                float* __restrict__ sw3, float* __restrict__ wt) {
    const int N1 = 8 * 27 * 7, N2 = 16 * 72 * 7, N3 = 32 * 144 * 7, NW = 100 * 512;
    int idx = blockIdx.x * blockDim.x + threadIdx.x;
    if (idx < N1)                    prep_sw_elem(c1_bw, c1_sw, c1_sc, sw1, idx, 27);
    else if (idx < N1 + N2)          prep_sw_elem(c2_bw, c2_sw, c2_sc, sw2, idx - N1, 72);
    else if (idx < N1 + N2 + N3)     prep_sw_elem(c3_bw, c3_sw, c3_sc, sw3, idx - N1 - N2, 144);
    else if (idx < N1 + N2 + N3 + NW) {
        int i = idx - N1 - N2 - N3;
        int o = i / 512, k = i % 512;
        wt[k * 100 + o] = lin_w[i];
    }
}

// ---------------- final linear: [256,512] @ [512,100]^T + b ----------------
__global__ void __launch_bounds__(128)
linear_kernel(const float* __restrict__ X, const float* __restrict__ WT,
              const float* __restrict__ bias, float* __restrict__ out) {
    __shared__ float xs[4][512];
    int b0 = blockIdx.x * 4;
    for (int i = threadIdx.x; i < 4 * 512; i += blockDim.x)
        xs[i / 512][i % 512] = X[(long)b0 * 512 + i];
    __syncthreads();
    int o = threadIdx.x;
    if (o >= 100) return;
    float acc0 = 0.f, acc1 = 0.f, acc2 = 0.f, acc3 = 0.f;
    for (int k = 0; k < 512; k++) {
        float w = WT[k * 100 + o];
        acc0 = fmaf(xs[0][k], w, acc0);
        acc1 = fmaf(xs[1][k], w, acc1);
        acc2 = fmaf(xs[2][k], w, acc2);
        acc3 = fmaf(xs[3][k], w, acc3);
    }
    float bb = bias[o];
    out[(b0 + 0) * 100 + o] = acc0 + bb;
    out[(b0 + 1) * 100 + o] = acc1 + bb;
    out[(b0 + 2) * 100 + o] = acc2 + bb;
    out[(b0 + 3) * 100 + o] = acc3 + bb;
}

// ---------------- launch ---------------------------------------------------
extern "C" void kernel_launch(void* const* d_in, const int* in_sizes, int n_in,
                              void* d_out, int out_size) {
    const float* x     = (const float*)d_in[0];
    const float* c1_bw = (const float*)d_in[1];
    const float* c1_sw = (const float*)d_in[2];
    const float* c1_sc = (const float*)d_in[3];
    const float* c2_bw = (const float*)d_in[4];
    const float* c2_sw = (const float*)d_in[5];
    const float* c2_sc = (const float*)d_in[6];
    const float* c3_bw = (const float*)d_in[7];
    const float* c3_sw = (const float*)d_in[8];
    const float* c3_sc = (const float*)d_in[9];
    const float* lin_w = (const float*)d_in[10];
    const float* lin_b = (const float*)d_in[11];
    float* out = (float*)d_out;

    float *p_bas1, *p_conv1, *p_bas2, *p_conv2, *p_bas3, *p_conv3, *p_pool3;
    float *p_sw1, *p_sw2, *p_sw3, *p_wt;
    cudaGetSymbolAddress((void**)&p_bas1,  d_bas1);
    cudaGetSymbolAddress((void**)&p_conv1, d_conv1);
    cudaGetSymbolAddress((void**)&p_bas2,  d_bas2);
    cudaGetSymbolAddress((void**)&p_conv2, d_conv2);
    cudaGetSymbolAddress((void**)&p_bas3,  d_bas3);
    cudaGetSymbolAddress((void**)&p_conv3, d_conv3);
    cudaGetSymbolAddress((void**)&p_pool3, d_pool3);
    cudaGetSymbolAddress((void**)&p_sw1,   d_sw1);
    cudaGetSymbolAddress((void**)&p_sw2,   d_sw2);
    cudaGetSymbolAddress((void**)&p_sw3,   d_sw3);
    cudaGetSymbolAddress((void**)&p_wt,    d_wt);

    // merged weight prep (1 launch)
    {
        int total = 8*27*7 + 16*72*7 + 32*144*7 + 100*512;
        prep_all_kernel<<<(total + 255) / 256, 256>>>(
            c1_bw, c1_sw, c1_sc, c2_bw, c2_sw, c2_sc, c3_bw, c3_sw, c3_sc,
            lin_w, p_sw1, p_sw2, p_sw3, p_wt);
    }
    // layer 1
    {
        int n = BATCH * 3 * 34 * 34;
        basis_in_kernel<3, 32><<<(n + 255) / 256, 256>>>(x, p_bas1);
        dim3 grid(BATCH * 32 * 16 / 128, 1);
        conv_kan_kernel<3, 32, 1><<<grid, 128>>>(p_bas1, p_sw1, p_conv1);
        int m = BATCH * 8 * 18 * 18;
        pool_basis_kernel<8, 32><<<(m + 255) / 256, 256>>>(p_conv1, p_bas2);
    }
    // layer 2
    {
        dim3 grid(BATCH * 16 * 8 / 128, 2);
        conv_kan_kernel<8, 16, 2><<<grid, 128>>>(p_bas2, p_sw2, p_conv2);
        int m = BATCH * 16 * 10 * 10;
        pool_basis_kernel<16, 16><<<(m + 255) / 256, 256>>>(p_conv2, p_bas3);
    }
    // layer 3
    {
        dim3 grid(BATCH * 8 * 4 / 128, 4);
        conv_kan_kernel<16, 8, 4><<<grid, 128>>>(p_bas3, p_sw3, p_conv3);
        int n = BATCH * 32 * 4 * 4;
        maxpool_kernel<<<(n + 255) / 256, 256>>>(p_conv3, p_pool3, n, 8);
    }
    // linear
    linear_kernel<<<BATCH / 4, 128>>>(p_pool3, p_wt, lin_b, out);
}